// round 3
// baseline (speedup 1.0000x reference)
#include <cuda_runtime.h>

// ---------------------------------------------------------------------------
// QuadraticConv2DTranspose, exploiting bed-of-nails sparsity.
//   B=8, H=W=32, CIN=COUT=64, k=3, stride=2 -> out [8,64,64,64]
// Per output-pixel parity class (ho%2, wo%2), the 3x3 patch over the
// upsampled buffer has only NT in {1,2,2,4} nonzero taps -> F in {2,5,5,14}
// non-bias features out of 55. We precompute compacted per-class kernels and
// a bias vector, then run a register-tiled fp32x2 "feature-GEMM".
// ---------------------------------------------------------------------------

// compacted kernels, flat: class0 @0 (2*4096), class1 @8192 (5*4096),
// class2 @28672 (5*4096), class3 @49152 (14*4096)  -> 106496 floats
__device__ float g_Kc[106496];
__device__ float g_bias[64];

__constant__ int c_L[4][14] = {
    {30,49, 0,0,0,0,0,0,0,0,0,0,0,0},
    {24,26,35,48,50, 0,0,0,0,0,0,0,0,0},
    { 9,15,42,46,52, 0,0,0,0,0,0,0,0,0},
    { 0, 2, 6, 8,17,21,23,39,41,44,45,47,51,53}
};
__constant__ int c_off[4] = {0, 8192, 28672, 49152};
__constant__ int c_Fn[4] = {2, 5, 5, 14};

// --------------------------- preprocessing ---------------------------------

__global__ void qct_compact(const float* __restrict__ fk) {
    int idx = blockIdx.x * 256 + threadIdx.x;        // over 4*14*4096
    if (idx >= 4 * 14 * 4096) return;
    int C = idx / (14 * 4096);
    int r = idx % (14 * 4096);
    int f = r / 4096;
    int co = r % 4096;
    int c = co >> 6, o = co & 63;
    int F = c_Fn[C];
    if (f >= F) return;
    g_Kc[c_off[C] + (c * F + f) * 64 + o] = fk[(c_L[C][f] * 64 + c) * 64 + o];
}

__global__ void qct_bias(const float* __restrict__ fk) {
    int o = threadIdx.x;
    float s = 0.f;
#pragma unroll 8
    for (int c = 0; c < 64; c++) s += fk[(54 * 64 + c) * 64 + o];
    g_bias[o] = s;
}

// --------------------------- f32x2 helpers ---------------------------------

__device__ __forceinline__ unsigned long long pack2(float v) {
    unsigned long long r;
    unsigned int u = __float_as_uint(v);
    asm("mov.b64 %0, {%1, %1};" : "=l"(r) : "r"(u));
    return r;
}
__device__ __forceinline__ void fma2(unsigned long long& d,
                                     unsigned long long a,
                                     unsigned long long b) {
    asm("fma.rn.f32x2 %0, %1, %2, %0;" : "+l"(d) : "l"(a), "l"(b));
}
__device__ __forceinline__ void unpack2(unsigned long long v, float& lo, float& hi) {
    unsigned int a, b;
    asm("mov.b64 {%0, %1}, %2;" : "=r"(a), "=r"(b) : "l"(v));
    lo = __uint_as_float(a);
    hi = __uint_as_float(b);
}

// --------------------------- class configs ---------------------------------
// __host__ __device__ constexpr accessor FUNCTIONS (no static member arrays,
// no --expt-relaxed-constexpr dependence). All call sites pass compile-time
// constants from fully unrolled loops, so these fold to immediates.

template <int C> struct Cfg;
template <> struct Cfg<0> {   // (ho even, wo even): tap j=4
    static constexpr int PY = 0, PX = 0, NT = 1, F = 2, OFF = 0;
    __host__ __device__ static constexpr int DR(int) { return 0; }
    __host__ __device__ static constexpr int DC(int) { return 0; }
    __host__ __device__ static constexpr int FA(int) { return 0; }
    __host__ __device__ static constexpr int FB(int f) { return f == 0 ? 0 : -1; }
};
template <> struct Cfg<1> {   // (even, odd): taps j=3,5 (cols j, j+1)
    static constexpr int PY = 0, PX = 1, NT = 2, F = 5, OFF = 8192;
    __host__ __device__ static constexpr int DR(int) { return 0; }
    __host__ __device__ static constexpr int DC(int a) { return a == 0 ? 0 : 1; }
    __host__ __device__ static constexpr int FA(int f) {
        return f == 0 ? 0 : f == 1 ? 0 : f == 2 ? 1 : f == 3 ? 0 : 1;
    }
    __host__ __device__ static constexpr int FB(int f) {
        return f == 0 ? 0 : f == 1 ? 1 : f == 2 ? 1 : -1;
    }
};
template <> struct Cfg<2> {   // (odd, even): taps j=1,7 (rows i, i+1)
    static constexpr int PY = 1, PX = 0, NT = 2, F = 5, OFF = 28672;
    __host__ __device__ static constexpr int DR(int a) { return a == 0 ? 0 : 1; }
    __host__ __device__ static constexpr int DC(int) { return 0; }
    __host__ __device__ static constexpr int FA(int f) {
        return f == 0 ? 0 : f == 1 ? 0 : f == 2 ? 1 : f == 3 ? 0 : 1;
    }
    __host__ __device__ static constexpr int FB(int f) {
        return f == 0 ? 0 : f == 1 ? 1 : f == 2 ? 1 : -1;
    }
};
template <> struct Cfg<3> {   // (odd, odd): taps j=0,2,6,8
    static constexpr int PY = 1, PX = 1, NT = 4, F = 14, OFF = 49152;
    __host__ __device__ static constexpr int DR(int a) { return a >> 1; }
    __host__ __device__ static constexpr int DC(int a) { return a & 1; }
    // quad pairs (0,0)(0,1)(0,2)(0,3)(1,1)(1,2)(1,3)(2,2)(2,3)(3,3), then linear 0..3
    __host__ __device__ static constexpr int FA(int f) {
        return f == 0 ? 0 : f == 1 ? 0 : f == 2 ? 0 : f == 3 ? 0
             : f == 4 ? 1 : f == 5 ? 1 : f == 6 ? 1
             : f == 7 ? 2 : f == 8 ? 2 : f == 9 ? 3
             : f == 10 ? 0 : f == 11 ? 1 : f == 12 ? 2 : 3;
    }
    __host__ __device__ static constexpr int FB(int f) {
        return f == 0 ? 0 : f == 1 ? 1 : f == 2 ? 2 : f == 3 ? 3
             : f == 4 ? 1 : f == 5 ? 2 : f == 6 ? 3
             : f == 7 ? 2 : f == 8 ? 3 : f == 9 ? 3 : -1;
    }
};

// --------------------------- main compute ----------------------------------
// CTA tile: one batch b, one input-row pair (i0=2*ipair .. +1), all 32 j's of
// one parity class -> 64 output pixels x 64 couts.
// Threads 256: tx = t&7 -> couts 8*tx..8*tx+7 ; ty = t>>3 -> pixels 2ty,2ty+1.
// smem: sK [16 cin][F][64] kernel slab chunk, sX taps [3 rows][33 cols][pad20].

template <int C>
__device__ __forceinline__ void run_tile(const float* __restrict__ x,
                                         float* __restrict__ out, int tile) {
    using Cf = Cfg<C>;
    constexpr int F = Cf::F;
    constexpr int NT = Cf::NT;

    extern __shared__ float sm[];
    float* sK = sm;                    // 16*F*64 floats
    float* sX = sm + 16 * F * 64;      // 3*33*20 floats

    const int b = tile >> 4;
    const int ipair = tile & 15;
    const int t = threadIdx.x;
    const int tx = t & 7;
    const int ty = t >> 3;
    const int m0 = 2 * ty;             // first pixel within tile
    const int ii = m0 >> 5;            // 0 or 1 (which input row of pair)
    const int j0 = m0 & 31;            // pixel-0 column index (even)

    unsigned long long acc[2][4];
#pragma unroll
    for (int p = 0; p < 2; p++)
#pragma unroll
        for (int q = 0; q < 4; q++) acc[p][q] = 0ull;

    const float* gK = g_Kc + Cf::OFF;

    for (int cc0 = 0; cc0 < 64; cc0 += 16) {
        __syncthreads();
        // ---- stage compacted kernel chunk: contiguous 16*F*64 floats ----
        {
            const float4* src = (const float4*)(gK + cc0 * F * 64);
            float4* dst = (float4*)sK;
#pragma unroll 4
            for (int idx = t; idx < F * 256; idx += 256) dst[idx] = src[idx];
        }
        // ---- stage taps: rows {2*ipair .. +2} x cols 0..32 x 16 cins ----
        for (int idx = t; idx < 3 * 33 * 4; idx += 256) {
            int c4 = idx & 3;
            int rc = idx >> 2;
            int cc = rc % 33;
            int rr = rc / 33;
            int r = ipair * 2 + rr;
            float4 v = make_float4(0.f, 0.f, 0.f, 0.f);
            if (r < 32 && cc < 32)
                v = *(const float4*)(x + (((b * 32 + r) * 32 + cc) << 6) + cc0 + c4 * 4);
            *(float4*)(sX + (rr * 33 + cc) * 20 + c4 * 4) = v;
        }
        __syncthreads();

#pragma unroll 2
        for (int cl = 0; cl < 16; cl++) {
            float tp[2][NT];
#pragma unroll
            for (int p = 0; p < 2; p++)
#pragma unroll
                for (int a = 0; a < NT; a++)
                    tp[p][a] = sX[((ii + Cf::DR(a)) * 33 + (j0 + p + Cf::DC(a))) * 20 + cl];

            const float* kbase = sK + cl * F * 64 + 8 * tx;
#pragma unroll
            for (int f = 0; f < F; f++) {
                const unsigned long long* kp = (const unsigned long long*)(kbase + f * 64);
                unsigned long long k0 = kp[0], k1 = kp[1], k2 = kp[2], k3 = kp[3];
#pragma unroll
                for (int p = 0; p < 2; p++) {
                    float fv = (Cf::FB(f) < 0)
                                   ? tp[p][Cf::FA(f)]
                                   : tp[p][Cf::FA(f)] * tp[p][Cf::FB(f)];
                    unsigned long long fpk = pack2(fv);
                    fma2(acc[p][0], fpk, k0);
                    fma2(acc[p][1], fpk, k1);
                    fma2(acc[p][2], fpk, k2);
                    fma2(acc[p][3], fpk, k3);
                }
            }
        }
    }

    // ---- epilogue: add bias, store 2 pixels x 8 couts ----
    float bo[8];
#pragma unroll
    for (int q = 0; q < 8; q++) bo[q] = g_bias[8 * tx + q];

    const int i = ipair * 2 + ii;
    const int ho = 2 * i + Cf::PY;
#pragma unroll
    for (int p = 0; p < 2; p++) {
        const int wo = 2 * (j0 + p) + Cf::PX;
        float v[8];
#pragma unroll
        for (int q = 0; q < 4; q++) unpack2(acc[p][q], v[2 * q], v[2 * q + 1]);
#pragma unroll
        for (int q = 0; q < 8; q++) v[q] += bo[q];
        float* op = out + (((b * 64 + ho) * 64 + wo) << 6) + 8 * tx;
        *(float4*)(op + 0) = make_float4(v[0], v[1], v[2], v[3]);
        *(float4*)(op + 4) = make_float4(v[4], v[5], v[6], v[7]);
    }
}

__global__ __launch_bounds__(256) void qct_main(const float* __restrict__ x,
                                                float* __restrict__ out) {
    int id = blockIdx.x;
    // heavy class 3 first for wave balance
    if (id < 128)      run_tile<3>(x, out, id);
    else if (id < 256) run_tile<1>(x, out, id - 128);
    else if (id < 384) run_tile<2>(x, out, id - 256);
    else               run_tile<0>(x, out, id - 384);
}

// --------------------------- launch ----------------------------------------

extern "C" void kernel_launch(void* const* d_in, const int* in_sizes, int n_in,
                              void* d_out, int out_size) {
    const float* x  = (const float*)d_in[0];
    const float* fk = (const float*)d_in[1];
    if (n_in >= 2 && in_sizes[0] == 55 * 64 * 64) {  // defensive order check
        const float* tmp = x; x = fk; fk = tmp;
    }
    float* out = (float*)d_out;

    qct_compact<<<(4 * 14 * 4096 + 255) / 256, 256>>>(fk);
    qct_bias<<<1, 64>>>(fk);

    const int smem_bytes = (16 * 14 * 64 + 3 * 33 * 20) * 4;  // 65264
    cudaFuncSetAttribute(qct_main, cudaFuncAttributeMaxDynamicSharedMemorySize,
                         smem_bytes);
    qct_main<<<512, 256, smem_bytes>>>(x, out);
}

// round 4
// speedup vs baseline: 1.6198x; 1.6198x over previous
#include <cuda_runtime.h>

// ---------------------------------------------------------------------------
// QuadraticConv2DTranspose, exploiting bed-of-nails sparsity.
//   B=8, H=W=32, CIN=COUT=64, k=3, stride=2 -> out [8,64,64,64]
// Per output parity class (ho%2,wo%2): NT in {1,2,2,4} nonzero taps ->
// F in {2,5,5,14} non-bias features of 55. Compacted per-class kernels +
// bias vector, then a register-tiled packed-fp32x2 "feature-GEMM".
// R4: 4 px/thread (2x kernel-fragment reuse), LDS.128 kernel loads,
//     pre-duplicated packed taps in smem (no pack MOVs, mul.rn.f32x2 feats).
// ---------------------------------------------------------------------------

typedef unsigned long long u64;

// compacted kernels: class0 @0 (2*4096), class1 @8192 (5*4096),
// class2 @28672 (5*4096), class3 @49152 (14*4096)
__device__ float g_Kc[106496];
__device__ float g_bias[64];

__constant__ int c_L[4][14] = {
    {30,49, 0,0,0,0,0,0,0,0,0,0,0,0},
    {24,26,35,48,50, 0,0,0,0,0,0,0,0,0},
    { 9,15,42,46,52, 0,0,0,0,0,0,0,0,0},
    { 0, 2, 6, 8,17,21,23,39,41,44,45,47,51,53}
};
__constant__ int c_off[4] = {0, 8192, 28672, 49152};
__constant__ int c_Fn[4] = {2, 5, 5, 14};

// --------------------------- preprocessing (fused) --------------------------

__global__ void qct_prep(const float* __restrict__ fk) {
    int idx = blockIdx.x * 256 + threadIdx.x;        // over 4*14*4096
    if (blockIdx.x == 0 && threadIdx.x < 64) {       // bias: sum over cin
        int o = threadIdx.x;
        float s = 0.f;
#pragma unroll 8
        for (int c = 0; c < 64; c++) s += fk[(54 * 64 + c) * 64 + o];
        g_bias[o] = s;
    }
    if (idx >= 4 * 14 * 4096) return;
    int C = idx / (14 * 4096);
    int r = idx % (14 * 4096);
    int f = r / 4096;
    int co = r % 4096;
    int c = co >> 6, o = co & 63;
    if (f >= c_Fn[C]) return;
    g_Kc[c_off[C] + (c * c_Fn[C] + f) * 64 + o] = fk[(c_L[C][f] * 64 + c) * 64 + o];
}

// --------------------------- f32x2 helpers ---------------------------------

__device__ __forceinline__ void fma2(u64& d, u64 a, u64 b) {
    asm("fma.rn.f32x2 %0, %1, %2, %0;" : "+l"(d) : "l"(a), "l"(b));
}
__device__ __forceinline__ u64 mul2(u64 a, u64 b) {
    u64 d;
    asm("mul.rn.f32x2 %0, %1, %2;" : "=l"(d) : "l"(a), "l"(b));
    return d;
}
__device__ __forceinline__ void unpack2(u64 v, float& lo, float& hi) {
    unsigned int a, b;
    asm("mov.b64 {%0, %1}, %2;" : "=r"(a), "=r"(b) : "l"(v));
    lo = __uint_as_float(a);
    hi = __uint_as_float(b);
}

// --------------------------- class configs ---------------------------------

template <int C> struct Cfg;
template <> struct Cfg<0> {   // (even, even): tap j=4
    static constexpr int PY = 0, PX = 0, NT = 1, F = 2, OFF = 0, NR = 1, NC = 4;
    __host__ __device__ static constexpr int DR(int) { return 0; }
    __host__ __device__ static constexpr int DC(int) { return 0; }
    __host__ __device__ static constexpr int FA(int) { return 0; }
    __host__ __device__ static constexpr int FB(int f) { return f == 0 ? 0 : -1; }
};
template <> struct Cfg<1> {   // (even, odd): taps j=3,5
    static constexpr int PY = 0, PX = 1, NT = 2, F = 5, OFF = 8192, NR = 1, NC = 5;
    __host__ __device__ static constexpr int DR(int) { return 0; }
    __host__ __device__ static constexpr int DC(int a) { return a == 0 ? 0 : 1; }
    __host__ __device__ static constexpr int FA(int f) {
        return f == 0 ? 0 : f == 1 ? 0 : f == 2 ? 1 : f == 3 ? 0 : 1;
    }
    __host__ __device__ static constexpr int FB(int f) {
        return f == 0 ? 0 : f == 1 ? 1 : f == 2 ? 1 : -1;
    }
};
template <> struct Cfg<2> {   // (odd, even): taps j=1,7
    static constexpr int PY = 1, PX = 0, NT = 2, F = 5, OFF = 28672, NR = 2, NC = 4;
    __host__ __device__ static constexpr int DR(int a) { return a == 0 ? 0 : 1; }
    __host__ __device__ static constexpr int DC(int) { return 0; }
    __host__ __device__ static constexpr int FA(int f) {
        return f == 0 ? 0 : f == 1 ? 0 : f == 2 ? 1 : f == 3 ? 0 : 1;
    }
    __host__ __device__ static constexpr int FB(int f) {
        return f == 0 ? 0 : f == 1 ? 1 : f == 2 ? 1 : -1;
    }
};
template <> struct Cfg<3> {   // (odd, odd): taps j=0,2,6,8
    static constexpr int PY = 1, PX = 1, NT = 4, F = 14, OFF = 49152, NR = 2, NC = 5;
    __host__ __device__ static constexpr int DR(int a) { return a >> 1; }
    __host__ __device__ static constexpr int DC(int a) { return a & 1; }
    __host__ __device__ static constexpr int FA(int f) {
        return f == 0 ? 0 : f == 1 ? 0 : f == 2 ? 0 : f == 3 ? 0
             : f == 4 ? 1 : f == 5 ? 1 : f == 6 ? 1
             : f == 7 ? 2 : f == 8 ? 2 : f == 9 ? 3
             : f == 10 ? 0 : f == 11 ? 1 : f == 12 ? 2 : 3;
    }
    __host__ __device__ static constexpr int FB(int f) {
        return f == 0 ? 0 : f == 1 ? 1 : f == 2 ? 2 : f == 3 ? 3
             : f == 4 ? 1 : f == 5 ? 2 : f == 6 ? 3
             : f == 7 ? 2 : f == 8 ? 3 : f == 9 ? 3 : -1;
    }
};

// --------------------------- main compute ----------------------------------
// CTA: one (b, class, input-row-pair) -> 64 output px x 64 couts.
// 128 threads: tx = t&7 -> couts 8tx..8tx+7 ; ty = t>>3 (16) -> px 4ty..4ty+3.
// cin chunked by 8. smem: sK[8 cin][F][64] floats; sXd[8][3 rows][34 cols]
// float2 taps stored DUPLICATED (v,v) so taps load pre-packed for f32x2.

#define CH 8

template <int C>
__device__ __forceinline__ void run_tile(const float* __restrict__ x,
                                         float* __restrict__ out, int tile) {
    using Cf = Cfg<C>;
    constexpr int F = Cf::F;

    extern __shared__ float sm[];
    float* sK = sm;                            // CH*F*64 floats
    float2* sXd = (float2*)(sm + CH * F * 64); // CH*3*34 float2

    const int b = tile >> 4;
    const int ipair = tile & 15;
    const int t = threadIdx.x;
    const int tx = t & 7;
    const int ty = t >> 3;                 // 0..15
    const int m0 = 4 * ty;                 // first of 4 pixels
    const int ii = m0 >> 5;                // input row within pair
    const int j0 = m0 & 31;                // first column (0,4,...,28)

    u64 acc[4][4];
#pragma unroll
    for (int p = 0; p < 4; p++)
#pragma unroll
        for (int q = 0; q < 4; q++) acc[p][q] = 0ull;

    const float* gK = g_Kc + Cf::OFF;

    for (int cc0 = 0; cc0 < 64; cc0 += CH) {
        __syncthreads();
        // ---- stage kernel chunk: contiguous CH*F*64 floats ----
        {
            const float4* src = (const float4*)(gK + cc0 * F * 64);
            float4* dst = (float4*)sK;
#pragma unroll
            for (int k = 0; k < F; k++) dst[k * 128 + t] = src[k * 128 + t];
        }
        // ---- stage taps duplicated: 99 (row,col) x 2 float4-groups ----
#pragma unroll
        for (int it = 0; it < 2; it++) {
            int idx = t + it * 128;
            if (idx < 198) {
                int g = idx & 1;
                int pos = idx >> 1;
                int rr = pos / 33, cc = pos % 33;
                int r = ipair * 2 + rr;
                float4 v = make_float4(0.f, 0.f, 0.f, 0.f);
                if (r < 32 && cc < 32)
                    v = *(const float4*)(x + (((b * 32 + r) * 32 + cc) << 6) + cc0 + 4 * g);
                float2* base = sXd + rr * 34 + cc;
                base[(4 * g + 0) * 102] = make_float2(v.x, v.x);
                base[(4 * g + 1) * 102] = make_float2(v.y, v.y);
                base[(4 * g + 2) * 102] = make_float2(v.z, v.z);
                base[(4 * g + 3) * 102] = make_float2(v.w, v.w);
            }
        }
        __syncthreads();

#pragma unroll 2
        for (int cl = 0; cl < CH; cl++) {
            // packed tap rows: rowv[r][c] = x[cin=cl, row ii+r, col j0+c] dup'd
            u64 rowv[Cf::NR][Cf::NC];
#pragma unroll
            for (int r = 0; r < Cf::NR; r++)
#pragma unroll
                for (int c = 0; c < Cf::NC; c++)
                    rowv[r][c] = *(const u64*)(sXd + (cl * 3 + ii + r) * 34 + j0 + c);

            const float* kbase = sK + cl * F * 64 + 8 * tx;
#pragma unroll
            for (int f = 0; f < F; f++) {
                const ulonglong2 ka = *(const ulonglong2*)(kbase + f * 64);
                const ulonglong2 kb = *(const ulonglong2*)(kbase + f * 64 + 4);
#pragma unroll
                for (int p = 0; p < 4; p++) {
                    u64 ta = rowv[Cf::DR(Cf::FA(f))][p + Cf::DC(Cf::FA(f))];
                    u64 pf;
                    if (Cf::FB(f) < 0) {
                        pf = ta;  // linear feature, already packed
                    } else {
                        u64 tb = rowv[Cf::DR(Cf::FB(f))][p + Cf::DC(Cf::FB(f))];
                        pf = mul2(ta, tb);
                    }
                    fma2(acc[p][0], pf, ka.x);
                    fma2(acc[p][1], pf, ka.y);
                    fma2(acc[p][2], pf, kb.x);
                    fma2(acc[p][3], pf, kb.y);
                }
            }
        }
    }

    // ---- epilogue: bias + store 4 px x 8 couts ----
    float4 b0 = *(const float4*)(g_bias + 8 * tx);
    float4 b1 = *(const float4*)(g_bias + 8 * tx + 4);

    const int i = ipair * 2 + ii;
    const int ho = 2 * i + Cf::PY;
#pragma unroll
    for (int p = 0; p < 4; p++) {
        const int wo = 2 * (j0 + p) + Cf::PX;
        float v[8];
#pragma unroll
        for (int q = 0; q < 4; q++) unpack2(acc[p][q], v[2 * q], v[2 * q + 1]);
        float* op = out + (((b * 64 + ho) * 64 + wo) << 6) + 8 * tx;
        *(float4*)(op + 0) = make_float4(v[0] + b0.x, v[1] + b0.y, v[2] + b0.z, v[3] + b0.w);
        *(float4*)(op + 4) = make_float4(v[4] + b1.x, v[5] + b1.y, v[6] + b1.z, v[7] + b1.w);
    }
}

__global__ __launch_bounds__(128) void qct_main(const float* __restrict__ x,
                                                float* __restrict__ out) {
    int id = blockIdx.x;
    // heavy class 3 first for wave balance / work-steal
    if (id < 128)      run_tile<3>(x, out, id);
    else if (id < 256) run_tile<1>(x, out, id - 128);
    else if (id < 384) run_tile<2>(x, out, id - 256);
    else               run_tile<0>(x, out, id - 384);
}

// --------------------------- launch ----------------------------------------

extern "C" void kernel_launch(void* const* d_in, const int* in_sizes, int n_in,
                              void* d_out, int out_size) {
    const float* x  = (const float*)d_in[0];
    const float* fk = (const float*)d_in[1];
    if (n_in >= 2 && in_sizes[0] == 55 * 64 * 64) {  // defensive order check
        const float* tmp = x; x = fk; fk = tmp;
    }
    float* out = (float*)d_out;

    qct_prep<<<(4 * 14 * 4096 + 255) / 256, 256>>>(fk);

    const int smem_bytes = (CH * 14 * 64 + CH * 3 * 34 * 2) * 4;  // 35200
    cudaFuncSetAttribute(qct_main, cudaFuncAttributeMaxDynamicSharedMemorySize,
                         smem_bytes);
    qct_main<<<512, 128, smem_bytes>>>(x, out);
}

// round 5
// speedup vs baseline: 1.7345x; 1.0708x over previous
#include <cuda_runtime.h>

// ---------------------------------------------------------------------------
// QuadraticConv2DTranspose via bed-of-nails sparsity.
//   B=8,H=W=32,CIN=COUT=64,k=3,s=2 -> out [8,64,64,64]
// Parity classes (ho%2,wo%2): NT {1,2,2,4} taps -> F {2,5,5,14} features.
// R5: cin-split 8-warp CTAs (2x occupancy), per-half named barriers,
//     gmem partial reduction. Inner loop: packed fp32x2 feature-GEMM.
// ---------------------------------------------------------------------------

typedef unsigned long long u64;

__device__ float g_Kc[106496];
__device__ float g_bias[64];

__constant__ int c_L[4][14] = {
    {30,49, 0,0,0,0,0,0,0,0,0,0,0,0},
    {24,26,35,48,50, 0,0,0,0,0,0,0,0,0},
    { 9,15,42,46,52, 0,0,0,0,0,0,0,0,0},
    { 0, 2, 6, 8,17,21,23,39,41,44,45,47,51,53}
};
__constant__ int c_off[4] = {0, 8192, 28672, 49152};
__constant__ int c_Fn[4] = {2, 5, 5, 14};

// --------------------------- preprocessing ---------------------------------

__global__ void qct_prep(const float* __restrict__ fk) {
    int idx = blockIdx.x * 256 + threadIdx.x;
    if (blockIdx.x == 0 && threadIdx.x < 64) {
        int o = threadIdx.x;
        float s = 0.f;
#pragma unroll 8
        for (int c = 0; c < 64; c++) s += fk[(54 * 64 + c) * 64 + o];
        g_bias[o] = s;
    }
    if (idx >= 4 * 14 * 4096) return;
    int C = idx / (14 * 4096);
    int r = idx % (14 * 4096);
    int f = r / 4096;
    int co = r % 4096;
    int c = co >> 6, o = co & 63;
    if (f >= c_Fn[C]) return;
    g_Kc[c_off[C] + (c * c_Fn[C] + f) * 64 + o] = fk[(c_L[C][f] * 64 + c) * 64 + o];
}

// --------------------------- f32x2 helpers ---------------------------------

__device__ __forceinline__ void fma2(u64& d, u64 a, u64 b) {
    asm("fma.rn.f32x2 %0, %1, %2, %0;" : "+l"(d) : "l"(a), "l"(b));
}
__device__ __forceinline__ u64 mul2(u64 a, u64 b) {
    u64 d;
    asm("mul.rn.f32x2 %0, %1, %2;" : "=l"(d) : "l"(a), "l"(b));
    return d;
}
__device__ __forceinline__ void unpack2(u64 v, float& lo, float& hi) {
    unsigned int a, b;
    asm("mov.b64 {%0, %1}, %2;" : "=r"(a), "=r"(b) : "l"(v));
    lo = __uint_as_float(a);
    hi = __uint_as_float(b);
}

// --------------------------- class configs ---------------------------------

template <int C> struct Cfg;
template <> struct Cfg<0> {   // (even, even): tap j=4
    static constexpr int PY = 0, PX = 0, F = 2, OFF = 0, NR = 1, NC = 4;
    __host__ __device__ static constexpr int DR(int) { return 0; }
    __host__ __device__ static constexpr int DC(int) { return 0; }
    __host__ __device__ static constexpr int FA(int) { return 0; }
    __host__ __device__ static constexpr int FB(int f) { return f == 0 ? 0 : -1; }
};
template <> struct Cfg<1> {   // (even, odd): taps j=3,5
    static constexpr int PY = 0, PX = 1, F = 5, OFF = 8192, NR = 1, NC = 5;
    __host__ __device__ static constexpr int DR(int) { return 0; }
    __host__ __device__ static constexpr int DC(int a) { return a == 0 ? 0 : 1; }
    __host__ __device__ static constexpr int FA(int f) {
        return f == 0 ? 0 : f == 1 ? 0 : f == 2 ? 1 : f == 3 ? 0 : 1;
    }
    __host__ __device__ static constexpr int FB(int f) {
        return f == 0 ? 0 : f == 1 ? 1 : f == 2 ? 1 : -1;
    }
};
template <> struct Cfg<2> {   // (odd, even): taps j=1,7
    static constexpr int PY = 1, PX = 0, F = 5, OFF = 28672, NR = 2, NC = 4;
    __host__ __device__ static constexpr int DR(int a) { return a == 0 ? 0 : 1; }
    __host__ __device__ static constexpr int DC(int) { return 0; }
    __host__ __device__ static constexpr int FA(int f) {
        return f == 0 ? 0 : f == 1 ? 0 : f == 2 ? 1 : f == 3 ? 0 : 1;
    }
    __host__ __device__ static constexpr int FB(int f) {
        return f == 0 ? 0 : f == 1 ? 1 : f == 2 ? 1 : -1;
    }
};
template <> struct Cfg<3> {   // (odd, odd): taps j=0,2,6,8
    static constexpr int PY = 1, PX = 1, F = 14, OFF = 49152, NR = 2, NC = 5;
    __host__ __device__ static constexpr int DR(int a) { return a >> 1; }
    __host__ __device__ static constexpr int DC(int a) { return a & 1; }
    __host__ __device__ static constexpr int FA(int f) {
        return f == 0 ? 0 : f == 1 ? 0 : f == 2 ? 0 : f == 3 ? 0
             : f == 4 ? 1 : f == 5 ? 1 : f == 6 ? 1
             : f == 7 ? 2 : f == 8 ? 2 : f == 9 ? 3
             : f == 10 ? 0 : f == 11 ? 1 : f == 12 ? 2 : 3;
    }
    __host__ __device__ static constexpr int FB(int f) {
        return f == 0 ? 0 : f == 1 ? 1 : f == 2 ? 2 : f == 3 ? 3
             : f == 4 ? 1 : f == 5 ? 2 : f == 6 ? 3
             : f == 7 ? 2 : f == 8 ? 3 : f == 9 ? 3 : -1;
    }
};

// --------------------------- main compute ----------------------------------
// CTA: 256 threads = two 128-thread halves; half h accumulates cin 32h..32h+31
// over its own smem staging buffers with its own named barrier. Each half:
// tx = th&7 -> couts 8tx..+7 ; ty = th>>3 -> pixels 4ty..+3 (64px x 64co tile).
// Reduction: half 1 stores partials to out, __syncthreads, half 0 adds+bias.

#define CH 8

template <int C>
__device__ __forceinline__ void run_tile(const float* __restrict__ x,
                                         float* __restrict__ out, int tile) {
    using Cf = Cfg<C>;
    constexpr int F = Cf::F;
    constexpr int KSZ = CH * F * 64;        // kernel chunk floats
    constexpr int TSZ = CH * 3 * 34 * 2;    // dup'd tap floats

    extern __shared__ float sm[];

    const int t = threadIdx.x;
    const int h = t >> 7;                  // cin half
    const int th = t & 127;
    float* sK = sm + h * (KSZ + TSZ);
    float2* sXd = (float2*)(sK + KSZ);

    const int b = tile >> 4;
    const int ipair = tile & 15;
    const int tx = th & 7;
    const int ty = th >> 3;
    const int m0 = 4 * ty;
    const int ii = m0 >> 5;
    const int j0 = m0 & 31;

    u64 acc[4][4];
#pragma unroll
    for (int p = 0; p < 4; p++)
#pragma unroll
        for (int q = 0; q < 4; q++) acc[p][q] = 0ull;

    const float* gK = g_Kc + Cf::OFF;

    for (int ch = 0; ch < 4; ch++) {
        const int cc0 = h * 32 + ch * CH;
        asm volatile("bar.sync %0, 128;" :: "r"(1 + h));
        // ---- stage kernel chunk: contiguous CH*F*64 floats ----
        {
            const float4* src = (const float4*)(gK + cc0 * F * 64);
            float4* dst = (float4*)sK;
#pragma unroll
            for (int k = 0; k < F; k++) dst[k * 128 + th] = src[k * 128 + th];
        }
        // ---- stage taps duplicated: 99 (row,col) x 2 float4-groups ----
#pragma unroll
        for (int it = 0; it < 2; it++) {
            int idx = th + it * 128;
            if (idx < 198) {
                int g = idx & 1;
                int pos = idx >> 1;
                int rr = pos / 33, cc = pos % 33;
                int r = ipair * 2 + rr;
                float4 v = make_float4(0.f, 0.f, 0.f, 0.f);
                if (r < 32 && cc < 32)
                    v = *(const float4*)(x + (((b * 32 + r) * 32 + cc) << 6) + cc0 + 4 * g);
                float2* base = sXd + rr * 34 + cc;
                base[(4 * g + 0) * 102] = make_float2(v.x, v.x);
                base[(4 * g + 1) * 102] = make_float2(v.y, v.y);
                base[(4 * g + 2) * 102] = make_float2(v.z, v.z);
                base[(4 * g + 3) * 102] = make_float2(v.w, v.w);
            }
        }
        asm volatile("bar.sync %0, 128;" :: "r"(1 + h));

#pragma unroll 2
        for (int cl = 0; cl < CH; cl++) {
            u64 rowv[Cf::NR][Cf::NC];
#pragma unroll
            for (int r = 0; r < Cf::NR; r++)
#pragma unroll
                for (int c = 0; c < Cf::NC; c++)
                    rowv[r][c] = *(const u64*)(sXd + (cl * 3 + ii + r) * 34 + j0 + c);

            const float* kbase = sK + cl * F * 64 + 8 * tx;
#pragma unroll
            for (int f = 0; f < F; f++) {
                const ulonglong2 ka = *(const ulonglong2*)(kbase + f * 64);
                const ulonglong2 kb = *(const ulonglong2*)(kbase + f * 64 + 4);
#pragma unroll
                for (int p = 0; p < 4; p++) {
                    u64 ta = rowv[Cf::DR(Cf::FA(f))][p + Cf::DC(Cf::FA(f))];
                    u64 pf;
                    if (Cf::FB(f) < 0) {
                        pf = ta;
                    } else {
                        u64 tb = rowv[Cf::DR(Cf::FB(f))][p + Cf::DC(Cf::FB(f))];
                        pf = mul2(ta, tb);
                    }
                    fma2(acc[p][0], pf, ka.x);
                    fma2(acc[p][1], pf, ka.y);
                    fma2(acc[p][2], pf, kb.x);
                    fma2(acc[p][3], pf, kb.y);
                }
            }
        }
    }

    // ---- reduction epilogue ----
    const int i = ipair * 2 + ii;
    const int ho = 2 * i + Cf::PY;

    if (h == 1) {   // store partials (cin 32..63)
#pragma unroll
        for (int p = 0; p < 4; p++) {
            const int wo = 2 * (j0 + p) + Cf::PX;
            float v[8];
#pragma unroll
            for (int q = 0; q < 4; q++) unpack2(acc[p][q], v[2 * q], v[2 * q + 1]);
            float* op = out + (((b * 64 + ho) * 64 + wo) << 6) + 8 * tx;
            *(float4*)(op + 0) = make_float4(v[0], v[1], v[2], v[3]);
            *(float4*)(op + 4) = make_float4(v[4], v[5], v[6], v[7]);
        }
    }
    __syncthreads();
    if (h == 0) {   // add partial + bias, final store
        float4 b0 = *(const float4*)(g_bias + 8 * tx);
        float4 b1 = *(const float4*)(g_bias + 8 * tx + 4);
#pragma unroll
        for (int p = 0; p < 4; p++) {
            const int wo = 2 * (j0 + p) + Cf::PX;
            float* op = out + (((b * 64 + ho) * 64 + wo) << 6) + 8 * tx;
            float4 o0 = *(const float4*)(op + 0);
            float4 o1 = *(const float4*)(op + 4);
            float v[8];
#pragma unroll
            for (int q = 0; q < 4; q++) unpack2(acc[p][q], v[2 * q], v[2 * q + 1]);
            *(float4*)(op + 0) = make_float4(v[0] + b0.x + o0.x, v[1] + b0.y + o0.y,
                                             v[2] + b0.z + o0.z, v[3] + b0.w + o0.w);
            *(float4*)(op + 4) = make_float4(v[4] + b1.x + o1.x, v[5] + b1.y + o1.y,
                                             v[6] + b1.z + o1.z, v[7] + b1.w + o1.w);
        }
    }
}

__global__ __launch_bounds__(256, 3) void qct_main(const float* __restrict__ x,
                                                   float* __restrict__ out) {
    int id = blockIdx.x;
    // heavy class 3 first for wave balance
    if (id < 128)      run_tile<3>(x, out, id);
    else if (id < 256) run_tile<1>(x, out, id - 128);
    else if (id < 384) run_tile<2>(x, out, id - 256);
    else               run_tile<0>(x, out, id - 384);
}

// --------------------------- launch ----------------------------------------

extern "C" void kernel_launch(void* const* d_in, const int* in_sizes, int n_in,
                              void* d_out, int out_size) {
    const float* x  = (const float*)d_in[0];
    const float* fk = (const float*)d_in[1];
    if (n_in >= 2 && in_sizes[0] == 55 * 64 * 64) {  // defensive order check
        const float* tmp = x; x = fk; fk = tmp;
    }
    float* out = (float*)d_out;

    qct_prep<<<(4 * 14 * 4096 + 255) / 256, 256>>>(fk);

    // two halves of (kernel chunk + dup'd taps), sized for class 3
    const int smem_bytes = 2 * (CH * 14 * 64 + CH * 3 * 34 * 2) * 4;  // 70400
    cudaFuncSetAttribute(qct_main, cudaFuncAttributeMaxDynamicSharedMemorySize,
                         smem_bytes);
    qct_main<<<512, 256, smem_bytes>>>(x, out);
}

// round 6
// speedup vs baseline: 2.3368x; 1.3472x over previous
#include <cuda_runtime.h>

// ---------------------------------------------------------------------------
// QuadraticConv2DTranspose via bed-of-nails sparsity.
//   B=8,H=W=32,CIN=COUT=64,k=3,s=2 -> out [8,64,64,64]
// Parity classes (ho%2,wo%2): NT {1,2,2,4} taps -> F {2,5,5,14} features.
// R6: 8px x 8co per thread (halves kernel-fragment smem bytes, the measured
//     L1 bottleneck). 128-thread CTAs = two 64-thread cin-halves, named
//     barriers, gmem partial reduction. Packed fp32x2 feature-GEMM inner loop.
// ---------------------------------------------------------------------------

typedef unsigned long long u64;

__device__ float g_Kc[106496];
__device__ float g_bias[64];

__constant__ int c_L[4][14] = {
    {30,49, 0,0,0,0,0,0,0,0,0,0,0,0},
    {24,26,35,48,50, 0,0,0,0,0,0,0,0,0},
    { 9,15,42,46,52, 0,0,0,0,0,0,0,0,0},
    { 0, 2, 6, 8,17,21,23,39,41,44,45,47,51,53}
};
__constant__ int c_off[4] = {0, 8192, 28672, 49152};
__constant__ int c_Fn[4] = {2, 5, 5, 14};

// --------------------------- preprocessing ---------------------------------

__global__ void qct_prep(const float* __restrict__ fk) {
    int idx = blockIdx.x * 256 + threadIdx.x;
    if (blockIdx.x == 0 && threadIdx.x < 64) {
        int o = threadIdx.x;
        float s = 0.f;
#pragma unroll 8
        for (int c = 0; c < 64; c++) s += fk[(54 * 64 + c) * 64 + o];
        g_bias[o] = s;
    }
    if (idx >= 4 * 14 * 4096) return;
    int C = idx / (14 * 4096);
    int r = idx % (14 * 4096);
    int f = r / 4096;
    int co = r % 4096;
    int c = co >> 6, o = co & 63;
    if (f >= c_Fn[C]) return;
    g_Kc[c_off[C] + (c * c_Fn[C] + f) * 64 + o] = fk[(c_L[C][f] * 64 + c) * 64 + o];
}

// --------------------------- f32x2 helpers ---------------------------------

__device__ __forceinline__ void fma2(u64& d, u64 a, u64 b) {
    asm("fma.rn.f32x2 %0, %1, %2, %0;" : "+l"(d) : "l"(a), "l"(b));
}
__device__ __forceinline__ u64 mul2(u64 a, u64 b) {
    u64 d;
    asm("mul.rn.f32x2 %0, %1, %2;" : "=l"(d) : "l"(a), "l"(b));
    return d;
}
__device__ __forceinline__ void unpack2(u64 v, float& lo, float& hi) {
    unsigned int a, b;
    asm("mov.b64 {%0, %1}, %2;" : "=r"(a), "=r"(b) : "l"(v));
    lo = __uint_as_float(a);
    hi = __uint_as_float(b);
}

// --------------------------- class configs ---------------------------------

template <int C> struct Cfg;
template <> struct Cfg<0> {   // (even, even): tap j=4
    static constexpr int PY = 0, PX = 0, F = 2, OFF = 0, NR = 1, NC = 8;
    __host__ __device__ static constexpr int DR(int) { return 0; }
    __host__ __device__ static constexpr int DC(int) { return 0; }
    __host__ __device__ static constexpr int FA(int) { return 0; }
    __host__ __device__ static constexpr int FB(int f) { return f == 0 ? 0 : -1; }
};
template <> struct Cfg<1> {   // (even, odd): taps j=3,5
    static constexpr int PY = 0, PX = 1, F = 5, OFF = 8192, NR = 1, NC = 9;
    __host__ __device__ static constexpr int DR(int) { return 0; }
    __host__ __device__ static constexpr int DC(int a) { return a == 0 ? 0 : 1; }
    __host__ __device__ static constexpr int FA(int f) {
        return f == 0 ? 0 : f == 1 ? 0 : f == 2 ? 1 : f == 3 ? 0 : 1;
    }
    __host__ __device__ static constexpr int FB(int f) {
        return f == 0 ? 0 : f == 1 ? 1 : f == 2 ? 1 : -1;
    }
};
template <> struct Cfg<2> {   // (odd, even): taps j=1,7
    static constexpr int PY = 1, PX = 0, F = 5, OFF = 28672, NR = 2, NC = 8;
    __host__ __device__ static constexpr int DR(int a) { return a == 0 ? 0 : 1; }
    __host__ __device__ static constexpr int DC(int) { return 0; }
    __host__ __device__ static constexpr int FA(int f) {
        return f == 0 ? 0 : f == 1 ? 0 : f == 2 ? 1 : f == 3 ? 0 : 1;
    }
    __host__ __device__ static constexpr int FB(int f) {
        return f == 0 ? 0 : f == 1 ? 1 : f == 2 ? 1 : -1;
    }
};
template <> struct Cfg<3> {   // (odd, odd): taps j=0,2,6,8
    static constexpr int PY = 1, PX = 1, F = 14, OFF = 49152, NR = 2, NC = 9;
    __host__ __device__ static constexpr int DR(int a) { return a >> 1; }
    __host__ __device__ static constexpr int DC(int a) { return a & 1; }
    __host__ __device__ static constexpr int FA(int f) {
        return f == 0 ? 0 : f == 1 ? 0 : f == 2 ? 0 : f == 3 ? 0
             : f == 4 ? 1 : f == 5 ? 1 : f == 6 ? 1
             : f == 7 ? 2 : f == 8 ? 2 : f == 9 ? 3
             : f == 10 ? 0 : f == 11 ? 1 : f == 12 ? 2 : 3;
    }
    __host__ __device__ static constexpr int FB(int f) {
        return f == 0 ? 0 : f == 1 ? 1 : f == 2 ? 2 : f == 3 ? 3
             : f == 4 ? 1 : f == 5 ? 2 : f == 6 ? 3
             : f == 7 ? 2 : f == 8 ? 3 : f == 9 ? 3 : -1;
    }
};

// --------------------------- main compute ----------------------------------
// CTA: 128 threads = two 64-thread cin-halves (h = t>>6), each with its own
// smem staging + named barrier. Per half: tx = th&7 -> couts 8tx..+7 ;
// tyy = th>>3 (0..7) -> 8 pixels starting at m0 = 8*tyy of the 64px tile.
// Reduction: half 1 stores partials to out, __syncthreads, half 0 adds+bias.

#define CH 8

template <int C>
__device__ __forceinline__ void run_tile(const float* __restrict__ x,
                                         float* __restrict__ out, int tile) {
    using Cf = Cfg<C>;
    constexpr int F = Cf::F;
    constexpr int KSZ = CH * F * 64;        // kernel chunk floats
    constexpr int TSZ = CH * 3 * 34 * 2;    // dup'd tap floats

    extern __shared__ float sm[];

    const int t = threadIdx.x;
    const int h = t >> 6;                   // cin half
    const int th = t & 63;
    float* sK = sm + h * (KSZ + TSZ);
    float2* sXd = (float2*)(sK + KSZ);

    const int b = tile >> 4;
    const int ipair = tile & 15;
    const int tx = th & 7;
    const int tyy = th >> 3;                // 0..7
    const int m0 = 8 * tyy;                 // first of 8 pixels
    const int ii = m0 >> 5;                 // input row within pair
    const int j0 = m0 & 31;                 // first column (0,8,16,24)

    u64 acc[8][4];
#pragma unroll
    for (int p = 0; p < 8; p++)
#pragma unroll
        for (int q = 0; q < 4; q++) acc[p][q] = 0ull;

    const float* gK = g_Kc + Cf::OFF;

    for (int ch = 0; ch < 4; ch++) {
        const int cc0 = h * 32 + ch * CH;
        asm volatile("bar.sync %0, 64;" :: "r"(1 + h));
        // ---- stage kernel chunk: contiguous CH*F*64 floats (F*128 float4) --
        {
            const float4* src = (const float4*)(gK + cc0 * F * 64);
            float4* dst = (float4*)sK;
#pragma unroll
            for (int k = 0; k < 2 * F; k++) dst[k * 64 + th] = src[k * 64 + th];
        }
        // ---- stage taps duplicated: 99 (row,col) x 2 float4-groups --------
#pragma unroll
        for (int it = 0; it < 4; it++) {
            int idx = th + it * 64;
            if (idx < 198) {
                int g = idx & 1;
                int pos = idx >> 1;
                int rr = pos / 33, cc = pos % 33;
                int r = ipair * 2 + rr;
                float4 v = make_float4(0.f, 0.f, 0.f, 0.f);
                if (r < 32 && cc < 32)
                    v = *(const float4*)(x + (((b * 32 + r) * 32 + cc) << 6) + cc0 + 4 * g);
                float2* base = sXd + rr * 34 + cc;
                base[(4 * g + 0) * 102] = make_float2(v.x, v.x);
                base[(4 * g + 1) * 102] = make_float2(v.y, v.y);
                base[(4 * g + 2) * 102] = make_float2(v.z, v.z);
                base[(4 * g + 3) * 102] = make_float2(v.w, v.w);
            }
        }
        asm volatile("bar.sync %0, 64;" :: "r"(1 + h));

        for (int cl = 0; cl < CH; cl++) {
            u64 rowv[Cf::NR][Cf::NC];
#pragma unroll
            for (int r = 0; r < Cf::NR; r++)
#pragma unroll
                for (int c = 0; c < Cf::NC; c++)
                    rowv[r][c] = *(const u64*)(sXd + (cl * 3 + ii + r) * 34 + j0 + c);

            const float* kbase = sK + cl * F * 64 + 8 * tx;
#pragma unroll
            for (int f = 0; f < F; f++) {
                const ulonglong2 ka = *(const ulonglong2*)(kbase + f * 64);
                const ulonglong2 kb = *(const ulonglong2*)(kbase + f * 64 + 4);
#pragma unroll
                for (int p = 0; p < 8; p++) {
                    u64 ta = rowv[Cf::DR(Cf::FA(f))][p + Cf::DC(Cf::FA(f))];
                    u64 pf;
                    if (Cf::FB(f) < 0) {
                        pf = ta;
                    } else {
                        u64 tb = rowv[Cf::DR(Cf::FB(f))][p + Cf::DC(Cf::FB(f))];
                        pf = mul2(ta, tb);
                    }
                    fma2(acc[p][0], pf, ka.x);
                    fma2(acc[p][1], pf, ka.y);
                    fma2(acc[p][2], pf, kb.x);
                    fma2(acc[p][3], pf, kb.y);
                }
            }
        }
    }

    // ---- reduction epilogue ----
    const int i = ipair * 2 + ii;
    const int ho = 2 * i + Cf::PY;

    if (h == 1) {   // store partials (cin 32..63)
#pragma unroll
        for (int p = 0; p < 8; p++) {
            const int wo = 2 * (j0 + p) + Cf::PX;
            float v[8];
#pragma unroll
            for (int q = 0; q < 4; q++) unpack2(acc[p][q], v[2 * q], v[2 * q + 1]);
            float* op = out + (((b * 64 + ho) * 64 + wo) << 6) + 8 * tx;
            *(float4*)(op + 0) = make_float4(v[0], v[1], v[2], v[3]);
            *(float4*)(op + 4) = make_float4(v[4], v[5], v[6], v[7]);
        }
    }
    __syncthreads();
    if (h == 0) {   // add partial + bias, final store
        float4 b0 = *(const float4*)(g_bias + 8 * tx);
        float4 b1 = *(const float4*)(g_bias + 8 * tx + 4);
#pragma unroll
        for (int p = 0; p < 8; p++) {
            const int wo = 2 * (j0 + p) + Cf::PX;
            float* op = out + (((b * 64 + ho) * 64 + wo) << 6) + 8 * tx;
            float4 o0 = *(const float4*)(op + 0);
            float4 o1 = *(const float4*)(op + 4);
            float v[8];
#pragma unroll
            for (int q = 0; q < 4; q++) unpack2(acc[p][q], v[2 * q], v[2 * q + 1]);
            *(float4*)(op + 0) = make_float4(v[0] + b0.x + o0.x, v[1] + b0.y + o0.y,
                                             v[2] + b0.z + o0.z, v[3] + b0.w + o0.w);
            *(float4*)(op + 4) = make_float4(v[4] + b1.x + o1.x, v[5] + b1.y + o1.y,
                                             v[6] + b1.z + o1.z, v[7] + b1.w + o1.w);
        }
    }
}

__global__ __launch_bounds__(128, 3) void qct_main(const float* __restrict__ x,
                                                   float* __restrict__ out) {
    int id = blockIdx.x;
    // heavy class 3 first for wave balance
    if (id < 128)      run_tile<3>(x, out, id);
    else if (id < 256) run_tile<1>(x, out, id - 128);
    else if (id < 384) run_tile<2>(x, out, id - 256);
    else               run_tile<0>(x, out, id - 384);
}

// --------------------------- launch ----------------------------------------

extern "C" void kernel_launch(void* const* d_in, const int* in_sizes, int n_in,
                              void* d_out, int out_size) {
    const float* x  = (const float*)d_in[0];
    const float* fk = (const float*)d_in[1];
    if (n_in >= 2 && in_sizes[0] == 55 * 64 * 64) {  // defensive order check
        const float* tmp = x; x = fk; fk = tmp;
    }
    float* out = (float*)d_out;

    qct_prep<<<(4 * 14 * 4096 + 255) / 256, 256>>>(fk);

    // two halves of (kernel chunk + dup'd taps), sized for class 3
    const int smem_bytes = 2 * (CH * 14 * 64 + CH * 3 * 34 * 2) * 4;  // 70400
    cudaFuncSetAttribute(qct_main, cudaFuncAttributeMaxDynamicSharedMemorySize,
                         smem_bytes);
    qct_main<<<512, 128, smem_bytes>>>(x, out);
}

// round 7
// speedup vs baseline: 2.4500x; 1.0484x over previous
#include <cuda_runtime.h>

// ---------------------------------------------------------------------------
// QuadraticConv2DTranspose via bed-of-nails sparsity.
//   B=8,H=W=32,CIN=COUT=64,k=3,s=2 -> out [8,64,64,64]
// Parity classes (ho%2,wo%2): NT {1,2,2,4} taps -> F {2,5,5,14} features.
// R7: Horner factorization (kills all feature mul2s, -14% fma instrs) +
//     cp.async double-buffered staging (CH=4, 2 bufs/half, same 70.4KB smem).
//     128-thr CTAs = two 64-thr cin-halves, named barriers, gmem reduction.
// ---------------------------------------------------------------------------

typedef unsigned long long u64;

__device__ float g_Kc[106496];
__device__ float g_bias[64];

// Horner-ordered feature lists: per tap a: quads (a,b) b=a..NT-1, then lin_a.
__constant__ int c_L[4][14] = {
    {30,49, 0,0,0,0,0,0,0,0,0,0,0,0},
    {24,26,48,35,50, 0,0,0,0,0,0,0,0,0},
    { 9,15,46,42,52, 0,0,0,0,0,0,0,0,0},
    { 0, 2, 6, 8,45,17,21,23,47,39,41,51,44,53}
};
__constant__ int c_off[4] = {0, 8192, 28672, 49152};
__constant__ int c_Fn[4] = {2, 5, 5, 14};

// --------------------------- preprocessing ---------------------------------

__global__ void qct_prep(const float* __restrict__ fk) {
    int idx = blockIdx.x * 256 + threadIdx.x;
    if (blockIdx.x == 0 && threadIdx.x < 64) {
        int o = threadIdx.x;
        float s = 0.f;
#pragma unroll 8
        for (int c = 0; c < 64; c++) s += fk[(54 * 64 + c) * 64 + o];
        g_bias[o] = s;
    }
    if (idx >= 4 * 14 * 4096) return;
    int C = idx / (14 * 4096);
    int r = idx % (14 * 4096);
    int f = r / 4096;
    int co = r % 4096;
    int c = co >> 6, o = co & 63;
    if (f >= c_Fn[C]) return;
    g_Kc[c_off[C] + (c * c_Fn[C] + f) * 64 + o] = fk[(c_L[C][f] * 64 + c) * 64 + o];
}

// --------------------------- helpers ---------------------------------------

__device__ __forceinline__ void fma2(u64& d, u64 a, u64 b) {
    asm("fma.rn.f32x2 %0, %1, %2, %0;" : "+l"(d) : "l"(a), "l"(b));
}
__device__ __forceinline__ void unpack2(u64 v, float& lo, float& hi) {
    unsigned int a, b;
    asm("mov.b64 {%0, %1}, %2;" : "=r"(a), "=r"(b) : "l"(v));
    lo = __uint_as_float(a);
    hi = __uint_as_float(b);
}
__device__ __forceinline__ void cp16(void* dst_smem, const void* src) {
    unsigned sdst = (unsigned)__cvta_generic_to_shared(dst_smem);
    asm volatile("cp.async.cg.shared.global [%0], [%1], 16;" :: "r"(sdst), "l"(src));
}
#define CP_COMMIT() asm volatile("cp.async.commit_group;")
template <int N>
__device__ __forceinline__ void cp_wait() {
    asm volatile("cp.async.wait_group %0;" :: "n"(N));
}

// --------------------------- class configs ---------------------------------
// Taps indexed a=0..NT-1 with patch offsets (DR,DC). Horner feature layout:
// FS(a) = start index of tap-a group; quads (a,b) at FS(a)+(b-a), lin at
// FS(a)+(NT-a).

template <int C> struct Cfg;
template <> struct Cfg<0> {   // (even, even): tap j=4
    static constexpr int PY = 0, PX = 0, F = 2, OFF = 0, NT = 1, NR = 1, NC = 8;
    __host__ __device__ static constexpr int DR(int) { return 0; }
    __host__ __device__ static constexpr int DC(int) { return 0; }
    __host__ __device__ static constexpr int FS(int a) {
        int s = 0; for (int i = 0; i < a; i++) s += NT - i + 1; return s;
    }
};
template <> struct Cfg<1> {   // (even, odd): taps j=3,5
    static constexpr int PY = 0, PX = 1, F = 5, OFF = 8192, NT = 2, NR = 1, NC = 9;
    __host__ __device__ static constexpr int DR(int) { return 0; }
    __host__ __device__ static constexpr int DC(int a) { return a; }
    __host__ __device__ static constexpr int FS(int a) {
        int s = 0; for (int i = 0; i < a; i++) s += NT - i + 1; return s;
    }
};
template <> struct Cfg<2> {   // (odd, even): taps j=1,7
    static constexpr int PY = 1, PX = 0, F = 5, OFF = 28672, NT = 2, NR = 2, NC = 8;
    __host__ __device__ static constexpr int DR(int a) { return a; }
    __host__ __device__ static constexpr int DC(int) { return 0; }
    __host__ __device__ static constexpr int FS(int a) {
        int s = 0; for (int i = 0; i < a; i++) s += NT - i + 1; return s;
    }
};
template <> struct Cfg<3> {   // (odd, odd): taps j=0,2,6,8
    static constexpr int PY = 1, PX = 1, F = 14, OFF = 49152, NT = 4, NR = 2, NC = 9;
    __host__ __device__ static constexpr int DR(int a) { return a >> 1; }
    __host__ __device__ static constexpr int DC(int a) { return a & 1; }
    __host__ __device__ static constexpr int FS(int a) {
        int s = 0; for (int i = 0; i < a; i++) s += NT - i + 1; return s;
    }
};

// --------------------------- staging ----------------------------------------
// Chunk = 4 cins. Kernel frags (4*F*64 floats) via cp.async; taps (3x33 px,
// 4 cins) LDG->STS stored DUPLICATED (v,v) for direct packed use.

template <int C>
__device__ __forceinline__ void stage(const float* __restrict__ x, float* sK,
                                      float2* sXd, const float* gK, int cc0,
                                      int b, int ipair, int th) {
    using Cf = Cfg<C>;
    const float4* src = (const float4*)(gK + cc0 * Cf::F * 64);
    float4* dst = (float4*)sK;
#pragma unroll
    for (int k = 0; k < Cf::F; k++)
        cp16(dst + k * 64 + th, src + k * 64 + th);
#pragma unroll
    for (int it = 0; it < 2; it++) {
        int idx = th + it * 64;
        if (idx < 99) {
            int rr = idx / 33, cc = idx % 33;
            int r = ipair * 2 + rr;
            float4 v = make_float4(0.f, 0.f, 0.f, 0.f);
            if (r < 32 && cc < 32)
                v = *(const float4*)(x + (((b * 32 + r) * 32 + cc) << 6) + cc0);
            float2* base = sXd + rr * 34 + cc;
            base[0 * 102] = make_float2(v.x, v.x);
            base[1 * 102] = make_float2(v.y, v.y);
            base[2 * 102] = make_float2(v.z, v.z);
            base[3 * 102] = make_float2(v.w, v.w);
        }
    }
}

// --------------------------- compute ----------------------------------------
// Horner: contribution = sum_a t_a * ( K_lin_a + sum_{b>=a} t_b * K_ab ).

template <int C>
__device__ __forceinline__ void compute_chunk(const float* sK, const float2* sXd,
                                              int ii, int j0, int tx,
                                              u64 acc[8][4]) {
    using Cf = Cfg<C>;
#pragma unroll
    for (int cl = 0; cl < 4; cl++) {
        u64 rowv[Cf::NR][Cf::NC];
#pragma unroll
        for (int r = 0; r < Cf::NR; r++)
#pragma unroll
            for (int c = 0; c < Cf::NC; c++)
                rowv[r][c] = *(const u64*)(sXd + (cl * 3 + ii + r) * 34 + j0 + c);

        const float* kbase = sK + cl * Cf::F * 64 + 8 * tx;
#pragma unroll
        for (int a = 0; a < Cf::NT; a++) {
            const int fs = Cf::FS(a);
            const int nb = Cf::NT - a;
            // linear frag (chain seed)
            const ulonglong2 la = *(const ulonglong2*)(kbase + (fs + nb) * 64);
            const ulonglong2 lb = *(const ulonglong2*)(kbase + (fs + nb) * 64 + 4);
            // quad frags for b = a..NT-1
            ulonglong2 qa[4], qb[4];
#pragma unroll
            for (int b = a; b < Cf::NT; b++) {
                qa[b - a] = *(const ulonglong2*)(kbase + (fs + b - a) * 64);
                qb[b - a] = *(const ulonglong2*)(kbase + (fs + b - a) * 64 + 4);
            }
#pragma unroll
            for (int p = 0; p < 8; p++) {
                u64 t0 = la.x, t1 = la.y, t2 = lb.x, t3 = lb.y;
#pragma unroll
                for (int b = Cf::NT - 1; b >= a; b--) {
                    u64 tb = rowv[Cf::DR(b)][p + Cf::DC(b)];
                    fma2(t0, tb, qa[b - a].x);
                    fma2(t1, tb, qa[b - a].y);
                    fma2(t2, tb, qb[b - a].x);
                    fma2(t3, tb, qb[b - a].y);
                }
                u64 ta = rowv[Cf::DR(a)][p + Cf::DC(a)];
                fma2(acc[p][0], ta, t0);
                fma2(acc[p][1], ta, t1);
                fma2(acc[p][2], ta, t2);
                fma2(acc[p][3], ta, t3);
            }
        }
    }
}

// --------------------------- main kernel ------------------------------------
// CTA: 128 threads = two 64-thread cin-halves (h = t>>6). Per half:
// tx = th&7 -> couts 8tx..+7 ; tyy = th>>3 -> 8 pixels at m0 = 8*tyy.
// 8 chunks of 4 cins, double-buffered. Reduction: h=1 stores partials to out,
// __syncthreads, h=0 adds partial + bias.

#define CH 4

template <int C>
__device__ __forceinline__ void run_tile(const float* __restrict__ x,
                                         float* __restrict__ out, int tile) {
    using Cf = Cfg<C>;
    constexpr int KSZ = CH * Cf::F * 64;      // kernel chunk floats
    constexpr int TSZ = CH * 3 * 34 * 2;      // dup'd tap floats
    constexpr int BUF = KSZ + TSZ;

    extern __shared__ float sm[];

    const int t = threadIdx.x;
    const int h = t >> 6;
    const int th = t & 63;
    float* base = sm + h * 2 * BUF;

    const int b = tile >> 4;
    const int ipair = tile & 15;
    const int tx = th & 7;
    const int tyy = th >> 3;
    const int m0 = 8 * tyy;
    const int ii = m0 >> 5;
    const int j0 = m0 & 31;

    u64 acc[8][4];
#pragma unroll
    for (int p = 0; p < 8; p++)
#pragma unroll
        for (int q = 0; q < 4; q++) acc[p][q] = 0ull;

    const float* gK = g_Kc + Cf::OFF;
    const int cbase = h * 32;

    // prologue: stage chunk 0 into buf 0
    stage<C>(x, base, (float2*)(base + KSZ), gK, cbase, b, ipair, th);
    CP_COMMIT();

    for (int ch = 0; ch < 8; ch++) {
        float* cbuf = base + (ch & 1) * BUF;
        float* nbuf = base + ((ch & 1) ^ 1) * BUF;
        if (ch < 7) {
            stage<C>(x, nbuf, (float2*)(nbuf + KSZ), gK, cbase + (ch + 1) * CH,
                     b, ipair, th);
            CP_COMMIT();
            cp_wait<1>();
        } else {
            cp_wait<0>();
        }
        asm volatile("bar.sync %0, 64;" :: "r"(1 + h));
        compute_chunk<C>(cbuf, (const float2*)(cbuf + KSZ), ii, j0, tx, acc);
        asm volatile("bar.sync %0, 64;" :: "r"(1 + h));
    }

    // ---- reduction epilogue ----
    const int i = ipair * 2 + ii;
    const int ho = 2 * i + Cf::PY;

    if (h == 1) {   // store partials (cin 32..63)
#pragma unroll
        for (int p = 0; p < 8; p++) {
            const int wo = 2 * (j0 + p) + Cf::PX;
            float v[8];
#pragma unroll
            for (int q = 0; q < 4; q++) unpack2(acc[p][q], v[2 * q], v[2 * q + 1]);
            float* op = out + (((b * 64 + ho) * 64 + wo) << 6) + 8 * tx;
            *(float4*)(op + 0) = make_float4(v[0], v[1], v[2], v[3]);
            *(float4*)(op + 4) = make_float4(v[4], v[5], v[6], v[7]);
        }
    }
    __syncthreads();
    if (h == 0) {   // add partial + bias, final store
        float4 b0 = *(const float4*)(g_bias + 8 * tx);
        float4 b1 = *(const float4*)(g_bias + 8 * tx + 4);
#pragma unroll
        for (int p = 0; p < 8; p++) {
            const int wo = 2 * (j0 + p) + Cf::PX;
            float* op = out + (((b * 64 + ho) * 64 + wo) << 6) + 8 * tx;
            float4 o0 = *(const float4*)(op + 0);
            float4 o1 = *(const float4*)(op + 4);
            float v[8];
#pragma unroll
            for (int q = 0; q < 4; q++) unpack2(acc[p][q], v[2 * q], v[2 * q + 1]);
            *(float4*)(op + 0) = make_float4(v[0] + b0.x + o0.x, v[1] + b0.y + o0.y,
                                             v[2] + b0.z + o0.z, v[3] + b0.w + o0.w);
            *(float4*)(op + 4) = make_float4(v[4] + b1.x + o1.x, v[5] + b1.y + o1.y,
                                             v[6] + b1.z + o1.z, v[7] + b1.w + o1.w);
        }
    }
}

__global__ __launch_bounds__(128, 3) void qct_main(const float* __restrict__ x,
                                                   float* __restrict__ out) {
    int id = blockIdx.x;
    // heavy class 3 first for wave balance
    if (id < 128)      run_tile<3>(x, out, id);
    else if (id < 256) run_tile<1>(x, out, id - 128);
    else if (id < 384) run_tile<2>(x, out, id - 256);
    else               run_tile<0>(x, out, id - 384);
}

// --------------------------- launch ----------------------------------------

extern "C" void kernel_launch(void* const* d_in, const int* in_sizes, int n_in,
                              void* d_out, int out_size) {
    const float* x  = (const float*)d_in[0];
    const float* fk = (const float*)d_in[1];
    if (n_in >= 2 && in_sizes[0] == 55 * 64 * 64) {  // defensive order check
        const float* tmp = x; x = fk; fk = tmp;
    }
    float* out = (float*)d_out;

    qct_prep<<<(4 * 14 * 4096 + 255) / 256, 256>>>(fk);

    // 2 halves x 2 buffers of (kernel chunk + dup'd taps), sized for class 3
    const int smem_bytes = 4 * (CH * 14 * 64 + CH * 3 * 34 * 2) * 4;  // 70400
    cudaFuncSetAttribute(qct_main, cudaFuncAttributeMaxDynamicSharedMemorySize,
                         smem_bytes);
    qct_main<<<512, 128, smem_bytes>>>(x, out);
}